// round 16
// baseline (speedup 1.0000x reference)
#include <cuda_runtime.h>
#include <cuda_fp16.h>
#include <cstdint>

#define B_   2
#define S_   2048
#define D_   1024
#define H_   16
#define HD_  64
#define M_   (B_ * S_)   // 4096
#define GN   D_
#define GK   D_

#define LOG2E  1.4426950408889634f
#define SC2    (0.125f * LOG2E)            // folded into Q projection
#define NEGM2  (-10000.0f * LOG2E)         // pad-mask additive (base-2)
#define MSHIFT 4.0f                        // fixed softmax shift
#define ONES2  0x3C003C00u                 // packed f16 {1, 1}

// ---------------- scratch (__device__ globals; no allocs allowed) ----------
__device__ __half g_Xh[M_ * GK];                     // rn(f16) X [M][K]
__device__ __half g_Wh[4][GK * GN];                  // W q/k/v/o rn(f16) [N][K]
__device__ __half g_Qh[M_ * D_];                     // head layout, pre-scaled
__device__ __half g_Kh[M_ * D_];
__device__ __half g_Vh[M_ * D_];
__device__ __half g_Ch[M_ * D_];                     // ctx rn(f16) [B,S,D]

// ---------------- PTX helpers (sm_80+ only; tcgen05 rejected here) ---------
__device__ __forceinline__ uint32_t smem_u32(const void* p) {
    uint32_t a;
    asm("{ .reg .u64 t; cvta.to.shared.u64 t, %1; cvt.u32.u64 %0, t; }"
        : "=r"(a) : "l"(p));
    return a;
}
#define SW(o) ((o) ^ (((o) >> 3) & 0x70))
__device__ __forceinline__ void cp16(uint32_t d, const void* g) {
    asm volatile("cp.async.cg.shared.global [%0], [%1], 16;" :: "r"(d), "l"(g) : "memory");
}
#define CP_COMMIT() asm volatile("cp.async.commit_group;" ::: "memory")
#define CP_WAIT0()  asm volatile("cp.async.wait_group 0;" ::: "memory")

__device__ __forceinline__ void ldsm4(uint32_t& r0, uint32_t& r1,
                                      uint32_t& r2, uint32_t& r3, uint32_t a) {
    asm volatile("ldmatrix.sync.aligned.m8n8.x4.shared.b16 {%0,%1,%2,%3}, [%4];"
                 : "=r"(r0), "=r"(r1), "=r"(r2), "=r"(r3) : "r"(a));
}
__device__ __forceinline__ void ldsm4t(uint32_t* r, uint32_t a) {
    asm volatile("ldmatrix.sync.aligned.m8n8.x4.trans.shared.b16 {%0,%1,%2,%3}, [%4];"
                 : "=r"(r[0]), "=r"(r[1]), "=r"(r[2]), "=r"(r[3]) : "r"(a));
}
__device__ __forceinline__ void mma_f16(float* c, const uint32_t* a,
                                        uint32_t b0, uint32_t b1) {
    asm volatile(
        "mma.sync.aligned.m16n8k16.row.col.f32.f16.f16.f32 "
        "{%0,%1,%2,%3}, {%4,%5,%6,%7}, {%8,%9}, {%0,%1,%2,%3};"
        : "+f"(c[0]), "+f"(c[1]), "+f"(c[2]), "+f"(c[3])
        : "r"(a[0]), "r"(a[1]), "r"(a[2]), "r"(a[3]), "r"(b0), "r"(b1));
}
__device__ __forceinline__ uint32_t h2u(__half2 h) {
    return *reinterpret_cast<uint32_t*>(&h);
}
__device__ __forceinline__ uint32_t rn2(float v0, float v1) {
    return h2u(__float22half2_rn(make_float2(v0, v1)));
}
__device__ __forceinline__ float ex2f(float x) {
    float y;
    asm("ex2.approx.ftz.f32 %0, %1;" : "=f"(y) : "f"(x));
    return y;
}

// ---------------- conversion kernels ----------------------------------------
__global__ __launch_bounds__(256) void rn_f16(
    const float* __restrict__ in, __half* __restrict__ out)
{
    int i = blockIdx.x * 256 + threadIdx.x;
    float4 v = ((const float4*)in)[i];
    ((uint32_t*)out)[2 * i]     = rn2(v.x, v.y);
    ((uint32_t*)out)[2 * i + 1] = rn2(v.z, v.w);
}

// All four W [K][N] f32 -> rn(f16) transposed [N][K]; blockIdx.z selects W
struct WPtrs { const float* w[4]; };
__global__ __launch_bounds__(256) void transpose_w_all(
    WPtrs ws, __half* __restrict__ whbase)
{
    __shared__ float t[32][33];
    const float* W = ws.w[blockIdx.z];
    __half* wh = whbase + (size_t)blockIdx.z * (GK * GN);
    const int n0 = blockIdx.x * 32, k0 = blockIdx.y * 32;
    const int tx = threadIdx.x, ty = threadIdx.y;   // (32, 8)
#pragma unroll
    for (int i = 0; i < 32; i += 8)
        t[ty + i][tx] = W[(size_t)(k0 + ty + i) * GN + n0 + tx];
    __syncthreads();
#pragma unroll
    for (int i = 0; i < 32; i += 8)
        wh[(size_t)(n0 + ty + i) * GK + k0 + tx] = __float2half_rn(t[tx][ty + i]);
}

// ---------------- f16 single-pass GEMM, 2-stage, correct ordering -----------
// (unchanged from R13/R15: WAIT0 -> sync -> prefetch -> compute; 64KB)
struct QKVOut {
    const float *bq, *bk, *bv;
    __half *qh, *kh, *vh;
};

#define G_LOAD(c) do {                                                       \
    uint32_t st_ = sb + ((c) & 1) * 32768;                                   \
    _Pragma("unroll")                                                        \
    for (int i_ = 0; i_ < 4; i_++) {                                         \
        int idx_ = tid + i_ * 256;                                           \
        int r_ = idx_ >> 3, u_ = idx_ & 7;                                   \
        uint32_t so_ = SW((uint32_t)(r_ * 128 + u_ * 16));                   \
        cp16(st_ + so_,         Ah + (size_t)(m0 + r_) * GK + (c) * 64 + u_ * 8); \
        cp16(st_ + 16384 + so_, Wh + (size_t)(n0 + r_) * GK + (c) * 64 + u_ * 8); \
    }                                                                        \
} while (0)

__global__ __launch_bounds__(256) void gemm1p(
    const __half* __restrict__ Ah, const __half* __restrict__ Whb, QKVOut op,
    const float* __restrict__ biasC, float* __restrict__ C, int mode)
{
    extern __shared__ char smc[];
    const uint32_t sb = smem_u32(smc);
    const int tid = threadIdx.x, lane = tid & 31, wid = tid >> 5;
    const int m0 = blockIdx.y * 128, n0 = blockIdx.x * 128;
    const int z = blockIdx.z;
    const __half* Wh = Whb + (mode ? (size_t)z * (GK * GN) : 0);
    const int wm = (wid & 3) * 32, wn = (wid >> 2) * 64;

    float acc[2][8][4];
#pragma unroll
    for (int mi = 0; mi < 2; mi++)
#pragma unroll
        for (int ni = 0; ni < 8; ni++)
#pragma unroll
            for (int r = 0; r < 4; r++) acc[mi][ni][r] = 0.0f;

    uint32_t aoff[2], boff[4];
#pragma unroll
    for (int mi = 0; mi < 2; mi++)
        aoff[mi] = (wm + mi * 16 + (lane & 15)) * 128 + ((lane >> 4) << 4);
#pragma unroll
    for (int nt = 0; nt < 4; nt++)
        boff[nt] = (wn + nt * 16 + (lane & 7) + ((lane >> 4) << 3)) * 128
                 + (((lane >> 3) & 1) << 4);

    G_LOAD(0); CP_COMMIT();

    for (int c = 0; c < 16; c++) {
        CP_WAIT0();                    // own copies of chunk c complete
        __syncthreads();               // chunk c visible; buf (c+1)&1 free
        if (c + 1 < 16) {
            G_LOAD(c + 1);
            CP_COMMIT();               // lands during compute(c)
        }

        const uint32_t sA = sb + (c & 1) * 32768;
        const uint32_t sW = sA + 16384;
#pragma unroll
        for (int k16 = 0; k16 < 4; k16++) {
            const uint32_t kb = k16 * 32;
            uint32_t a[2][4], w[4][4];
            ldsm4(a[0][0], a[0][1], a[0][2], a[0][3], sA + SW(aoff[0] + kb));
            ldsm4(a[1][0], a[1][1], a[1][2], a[1][3], sA + SW(aoff[1] + kb));
#pragma unroll
            for (int nt = 0; nt < 4; nt++)
                ldsm4(w[nt][0], w[nt][1], w[nt][2], w[nt][3],
                      sW + SW(boff[nt] + kb));
#pragma unroll
            for (int mi = 0; mi < 2; mi++)
#pragma unroll
                for (int ni = 0; ni < 8; ni++)
                    mma_f16(acc[mi][ni], a[mi],
                            w[ni >> 1][(ni & 1) * 2], w[ni >> 1][(ni & 1) * 2 + 1]);
        }
    }

    // epilogue
    const float* bias = mode ? ((z == 0) ? op.bq : (z == 1) ? op.bk : op.bv)
                             : biasC;
    const float osc = (mode == 1 && z == 0) ? SC2 : 1.0f;  // fold score scale
    const int r0 = lane >> 2, cq = (lane & 3) * 2;
#pragma unroll
    for (int mi = 0; mi < 2; mi++) {
#pragma unroll
        for (int ni = 0; ni < 8; ni++) {
            const int rr = m0 + wm + mi * 16 + r0;
            const int cc = n0 + wn + ni * 8 + cq;
            const float2 bv = *(const float2*)&bias[cc];
            float v0 = (acc[mi][ni][0] + bv.x) * osc;
            float v1 = (acc[mi][ni][1] + bv.y) * osc;
            float v2 = (acc[mi][ni][2] + bv.x) * osc;
            float v3 = (acc[mi][ni][3] + bv.y) * osc;
            if (mode == 0) {
                *(float2*)&C[(size_t)rr * GN + cc] = make_float2(v0, v1);
                *(float2*)&C[(size_t)(rr + 8) * GN + cc] = make_float2(v2, v3);
            } else {
                const int h = cc >> 6, d = cc & 63;
                const int bb = rr >> 11;
                const int s0 = rr & 2047, s1 = (rr + 8) & 2047;
                const size_t o0 = ((((size_t)bb * H_ + h) * S_ + s0) << 6) + d;
                const size_t o1 = ((((size_t)bb * H_ + h) * S_ + s1) << 6) + d;
                __half* oh = (z == 0) ? op.qh : (z == 1) ? op.kh : op.vh;
                *(uint32_t*)(oh + o0) = rn2(v0, v1);
                *(uint32_t*)(oh + o1) = rn2(v2, v3);
            }
        }
    }
}

// ---------------- f16 flash attention (hoisted Q + eager f16 P) -------------
// CTA: 128 threads (4 warps x 16 q = 64 q) x (b,h); 40.5KB smem;
// __launch_bounds__(128,4) pins <=128 regs -> 4 CTAs/SM.
// Full-tile QK (8 accumulators) -> mask -> ALL scores ex2+packed to aP[4][4]
// (fp32 s dies before PV -> smaller live set) -> PV (8 streams).
// P = 2^(s + mask - M); l via all-ones mma. Q pre-scaled by SC2.
#define ATT_STAGE(kt) do {                                                   \
    uint32_t st_ = SST + ((kt) & 1) * 16384;                                 \
    const size_t roff_ = base + (size_t)((kt) * 64) * HD_;                   \
    _Pragma("unroll")                                                        \
    for (int i_ = 0; i_ < 4; i_++) {                                         \
        int idx_ = tid + i_ * 128;                                           \
        int r_ = idx_ >> 3, u_ = idx_ & 7;                                   \
        uint32_t so_ = SW((uint32_t)(r_ * 128 + u_ * 16));                   \
        size_t go_ = roff_ + (size_t)r_ * HD_ + u_ * 8;                      \
        cp16(st_ + so_,        Kh_ + go_);                                   \
        cp16(st_ + 8192 + so_, Vh_ + go_);                                   \
    }                                                                        \
    if (tid < 64)                                                            \
        smaskf[((kt) & 1) * 64 + tid] =                                      \
            (1.0f - mask[b * S_ + (kt) * 64 + tid]) * NEGM2 - MSHIFT;        \
} while (0)

__global__ __launch_bounds__(128, 4) void attn_tc(
    const __half* __restrict__ Qh_, const __half* __restrict__ Kh_,
    const __half* __restrict__ Vh_, const float* __restrict__ mask,
    __half* __restrict__ ctxh)
{
    extern __shared__ char smraw[];
    const uint32_t sb = smem_u32(smraw);
    const uint32_t SQH = sb;                    // Q: 64 x 128B = 8KB
    const uint32_t SST = sb + 8192;             // 2 stages x 16KB
    float* smaskf = (float*)(smraw + 40960);    // 2 x 64 floats

    const int tid = threadIdx.x, lane = tid & 31, wid = tid >> 5;
    const int qt = gridDim.x - 1 - blockIdx.x;  // heavy tiles first
    const int q0 = qt * 64;
    const int bh = blockIdx.y;
    const int b = bh >> 4, hh = bh & 15;
    const size_t base = (size_t)bh * (S_ * HD_);
    const int wq = wid * 16;

    // Stage Q tile into smem (same cp.async group as stage 0)
    {
        const size_t qoff = base + (size_t)q0 * HD_;
#pragma unroll
        for (int i = 0; i < 4; i++) {
            int idx = tid + i * 128;
            int r = idx >> 3, u = idx & 7;
            cp16(SQH + SW((uint32_t)(r * 128 + u * 16)),
                 Qh_ + qoff + (size_t)r * HD_ + u * 8);
        }
    }
    const int ntile = qt + 1;
    ATT_STAGE(0);
    CP_COMMIT();

    const uint32_t arow = (wq + (lane & 15)) * 128 + ((lane >> 4) << 4);
    const uint32_t bno  = ((lane & 7) + ((lane >> 4) << 3)) * 128
                        + (((lane >> 3) & 1) << 4);
    const uint32_t vro  = (((lane >> 3) & 1) * 8 + (lane & 7)) * 128
                        + ((lane >> 4) << 4);
    const int c0  = (lane & 3) * 2;
    const int rg0 = q0 + wq + (lane >> 2);
    const int rg1 = rg0 + 8;

    uint32_t qf[4][4];                          // hoisted Q fragments
    float o[8][4];
#pragma unroll
    for (int ni = 0; ni < 8; ni++)
#pragma unroll
        for (int r = 0; r < 4; r++) o[ni][r] = 0.0f;
    float lacc[4] = {0.0f, 0.0f, 0.0f, 0.0f};   // row sums via ones-mma

    for (int kt = 0; kt < ntile; kt++) {
        CP_WAIT0();                    // own copies of stage kt complete
        __syncthreads();               // stage kt visible; buf (kt+1)&1 free
        if (kt == 0) {                 // Q resident: hoist fragments once
#pragma unroll
            for (int k16 = 0; k16 < 4; k16++)
                ldsm4(qf[k16][0], qf[k16][1], qf[k16][2], qf[k16][3],
                      SQH + SW(arow + k16 * 32));
        }
        if (kt + 1 < ntile) {
            ATT_STAGE(kt + 1);
            CP_COMMIT();               // lands during compute(kt)
        }

        const int k0 = kt * 64;
        if (k0 <= q0 + wq + 15) {      // warp-granular causal tile skip
            const uint32_t sKh = SST + (kt & 1) * 16384;
            const uint32_t sVh = sKh + 8192;

            uint32_t aP[4][4];         // packed f16 P for the whole tile
            {
                float s[8][4];
#pragma unroll
                for (int ni = 0; ni < 8; ni++)
#pragma unroll
                    for (int r = 0; r < 4; r++) s[ni][r] = 0.0f;

                // ---- S = Q.K (full tile: 8 independent streams) ----
#pragma unroll
                for (int k16 = 0; k16 < 4; k16++) {
                    const uint32_t kb = k16 * 32;
                    uint32_t kf[4][4];
#pragma unroll
                    for (int nt = 0; nt < 4; nt++)
                        ldsm4(kf[nt][0], kf[nt][1], kf[nt][2], kf[nt][3],
                              sKh + SW(bno + nt * 2048 + kb));
#pragma unroll
                    for (int ni = 0; ni < 8; ni++)
                        mma_f16(s[ni], qf[k16], kf[ni >> 1][(ni & 1) * 2],
                                kf[ni >> 1][(ni & 1) * 2 + 1]);
                }

                // ---- mask(+M shift) add + causal ----
                const float* mrow = smaskf + (kt & 1) * 64;
                const bool needc = (k0 + 63 > q0 + wq);
#pragma unroll
                for (int ni = 0; ni < 8; ni++) {
                    const int kg = k0 + ni * 8 + c0;
                    const float ma = mrow[ni * 8 + c0];
                    const float mb = mrow[ni * 8 + c0 + 1];
                    s[ni][0] += ma;
                    s[ni][1] += mb;
                    s[ni][2] += ma;
                    s[ni][3] += mb;
                    if (needc) {
                        if (kg > rg0)     s[ni][0] -= 1e10f;
                        if (kg + 1 > rg0) s[ni][1] -= 1e10f;
                        if (kg > rg1)     s[ni][2] -= 1e10f;
                        if (kg + 1 > rg1) s[ni][3] -= 1e10f;
                    }
                }

                // ---- P = 2^s for ALL jb; s (fp32) dies here ----
#pragma unroll
                for (int jb = 0; jb < 4; jb++) {
#pragma unroll
                    for (int t = 0; t < 2; t++) {
                        const int ti = jb * 2 + t;
                        aP[jb][t * 2 + 0] = rn2(ex2f(s[ti][0]), ex2f(s[ti][1]));
                        aP[jb][t * 2 + 1] = rn2(ex2f(s[ti][2]), ex2f(s[ti][3]));
                    }
                }
            }

            // ---- O += rn(P).V; l += rn(P).ones ----
#pragma unroll
            for (int jb = 0; jb < 4; jb++) {
                uint32_t vf[4][4];
                const uint32_t vbase = vro + jb * 2048;
#pragma unroll
                for (int nt = 0; nt < 4; nt++)
                    ldsm4t(vf[nt], sVh + SW(vbase + nt * 32));
#pragma unroll
                for (int ni = 0; ni < 8; ni++)
                    mma_f16(o[ni], aP[jb], vf[ni >> 1][(ni & 1) * 2],
                            vf[ni >> 1][(ni & 1) * 2 + 1]);
                mma_f16(lacc, aP[jb], ONES2, ONES2);
            }
        }
    }

    // ---- normalize + write ctx rn(f16) in [B,S,D] layout ----
    const float i0 = 1.0f / lacc[0], i1 = 1.0f / lacc[2];
    const size_t row0 = ((size_t)b * S_ + rg0) * D_ + hh * HD_;
    const size_t row1 = ((size_t)b * S_ + rg1) * D_ + hh * HD_;
#pragma unroll
    for (int ni = 0; ni < 8; ni++) {
        const int d = ni * 8 + c0;
        *(uint32_t*)(ctxh + row0 + d) = rn2(o[ni][0] * i0, o[ni][1] * i0);
        *(uint32_t*)(ctxh + row1 + d) = rn2(o[ni][2] * i1, o[ni][3] * i1);
    }
}

// ---------------------------------------------------------------------------
extern "C" void kernel_launch(void* const* d_in, const int* in_sizes, int n_in,
                              void* d_out, int out_size)
{
    const float* X    = (const float*)d_in[0];
    const float* mask = (const float*)d_in[1];
    const float* Wq   = (const float*)d_in[2];
    const float* bq   = (const float*)d_in[3];
    const float* Wk   = (const float*)d_in[4];
    const float* bk   = (const float*)d_in[5];
    const float* Wv   = (const float*)d_in[6];
    const float* bv   = (const float*)d_in[7];
    const float* Wo   = (const float*)d_in[8];
    const float* bo   = (const float*)d_in[9];
    float* out = (float*)d_out;

    __half *pXh, *pWh, *pQh, *pKh, *pVh, *pCh;
    cudaGetSymbolAddress((void**)&pXh, g_Xh);
    cudaGetSymbolAddress((void**)&pWh, g_Wh);
    cudaGetSymbolAddress((void**)&pQh, g_Qh);
    cudaGetSymbolAddress((void**)&pKh, g_Kh);
    cudaGetSymbolAddress((void**)&pVh, g_Vh);
    cudaGetSymbolAddress((void**)&pCh, g_Ch);

    const int GEMM_SMEM = 2 * 32768;                 // 64 KB -> 3 CTAs/SM
    cudaFuncSetAttribute(gemm1p, cudaFuncAttributeMaxDynamicSharedMemorySize,
                         GEMM_SMEM);
    const int ATTN_SMEM = 40960 + 512;               // 40.5 KB -> 4 CTAs/SM
    cudaFuncSetAttribute(attn_tc, cudaFuncAttributeMaxDynamicSharedMemorySize,
                         ATTN_SMEM);

    const size_t WSZ = (size_t)GK * GN;

    rn_f16<<<M_ * GK / 1024, 256>>>(X, pXh);
    WPtrs ws = {{Wq, Wk, Wv, Wo}};
    transpose_w_all<<<dim3(GN / 32, GK / 32, 4), dim3(32, 8)>>>(ws, pWh);

    QKVOut op = {bq, bk, bv, pQh, pKh, pVh};
    gemm1p<<<dim3(GN / 128, M_ / 128, 3), 256, GEMM_SMEM>>>(
        pXh, pWh, op, nullptr, nullptr, 1);

    dim3 ga(S_ / 64, B_ * H_);     // (32, 32) x 128 threads
    attn_tc<<<ga, 128, ATTN_SMEM>>>(pQh, pKh, pVh, mask, pCh);

    gemm1p<<<dim3(GN / 128, M_ / 128, 1), 256, GEMM_SMEM>>>(
        pCh, pWh + 3 * WSZ, op, bo, out, 0);
}

// round 17
// speedup vs baseline: 1.0329x; 1.0329x over previous
#include <cuda_runtime.h>
#include <cuda_fp16.h>
#include <cstdint>

#define B_   2
#define S_   2048
#define D_   1024
#define H_   16
#define HD_  64
#define M_   (B_ * S_)   // 4096
#define GN   D_
#define GK   D_

#define LOG2E  1.4426950408889634f
#define SC2    (0.125f * LOG2E)            // folded into Q projection
#define NEGM2  (-10000.0f * LOG2E)         // pad-mask additive (base-2)
#define MSHIFT 4.0f                        // fixed softmax shift
#define ONES2  0x3C003C00u                 // packed f16 {1, 1}

// ---------------- scratch (__device__ globals; no allocs allowed) ----------
__device__ __half g_Xh[M_ * GK];                     // rn(f16) X [M][K]
__device__ __half g_Wh[4][GK * GN];                  // W q/k/v/o rn(f16) [N][K]
__device__ __half g_Qh[M_ * D_];                     // head layout, pre-scaled
__device__ __half g_Kh[M_ * D_];
__device__ __half g_Vh[M_ * D_];
__device__ __half g_Ch[M_ * D_];                     // ctx rn(f16) [B,S,D]

// ---------------- PTX helpers (sm_80+ only; tcgen05 rejected here) ---------
__device__ __forceinline__ uint32_t smem_u32(const void* p) {
    uint32_t a;
    asm("{ .reg .u64 t; cvta.to.shared.u64 t, %1; cvt.u32.u64 %0, t; }"
        : "=r"(a) : "l"(p));
    return a;
}
#define SW(o) ((o) ^ (((o) >> 3) & 0x70))
__device__ __forceinline__ void cp16(uint32_t d, const void* g) {
    asm volatile("cp.async.cg.shared.global [%0], [%1], 16;" :: "r"(d), "l"(g) : "memory");
}
#define CP_COMMIT() asm volatile("cp.async.commit_group;" ::: "memory")
#define CP_WAIT0()  asm volatile("cp.async.wait_group 0;" ::: "memory")

__device__ __forceinline__ void ldsm4(uint32_t& r0, uint32_t& r1,
                                      uint32_t& r2, uint32_t& r3, uint32_t a) {
    asm volatile("ldmatrix.sync.aligned.m8n8.x4.shared.b16 {%0,%1,%2,%3}, [%4];"
                 : "=r"(r0), "=r"(r1), "=r"(r2), "=r"(r3) : "r"(a));
}
__device__ __forceinline__ void ldsm4t(uint32_t* r, uint32_t a) {
    asm volatile("ldmatrix.sync.aligned.m8n8.x4.trans.shared.b16 {%0,%1,%2,%3}, [%4];"
                 : "=r"(r[0]), "=r"(r[1]), "=r"(r[2]), "=r"(r[3]) : "r"(a));
}
__device__ __forceinline__ void mma_f16(float* c, const uint32_t* a,
                                        uint32_t b0, uint32_t b1) {
    asm volatile(
        "mma.sync.aligned.m16n8k16.row.col.f32.f16.f16.f32 "
        "{%0,%1,%2,%3}, {%4,%5,%6,%7}, {%8,%9}, {%0,%1,%2,%3};"
        : "+f"(c[0]), "+f"(c[1]), "+f"(c[2]), "+f"(c[3])
        : "r"(a[0]), "r"(a[1]), "r"(a[2]), "r"(a[3]), "r"(b0), "r"(b1));
}
__device__ __forceinline__ uint32_t h2u(__half2 h) {
    return *reinterpret_cast<uint32_t*>(&h);
}
__device__ __forceinline__ uint32_t rn2(float v0, float v1) {
    return h2u(__float22half2_rn(make_float2(v0, v1)));
}
__device__ __forceinline__ float ex2f(float x) {
    float y;
    asm("ex2.approx.ftz.f32 %0, %1;" : "=f"(y) : "f"(x));
    return y;
}

// ---------------- conversion kernels ----------------------------------------
__global__ __launch_bounds__(256) void rn_f16(
    const float* __restrict__ in, __half* __restrict__ out)
{
    int i = blockIdx.x * 256 + threadIdx.x;
    float4 v = ((const float4*)in)[i];
    ((uint32_t*)out)[2 * i]     = rn2(v.x, v.y);
    ((uint32_t*)out)[2 * i + 1] = rn2(v.z, v.w);
}

// All four W [K][N] f32 -> rn(f16) transposed [N][K]; blockIdx.z selects W
struct WPtrs { const float* w[4]; };
__global__ __launch_bounds__(256) void transpose_w_all(
    WPtrs ws, __half* __restrict__ whbase)
{
    __shared__ float t[32][33];
    const float* W = ws.w[blockIdx.z];
    __half* wh = whbase + (size_t)blockIdx.z * (GK * GN);
    const int n0 = blockIdx.x * 32, k0 = blockIdx.y * 32;
    const int tx = threadIdx.x, ty = threadIdx.y;   // (32, 8)
#pragma unroll
    for (int i = 0; i < 32; i += 8)
        t[ty + i][tx] = W[(size_t)(k0 + ty + i) * GN + n0 + tx];
    __syncthreads();
#pragma unroll
    for (int i = 0; i < 32; i += 8)
        wh[(size_t)(n0 + ty + i) * GK + k0 + tx] = __float2half_rn(t[tx][ty + i]);
}

// ---------------- f16 single-pass GEMM, 2-stage, correct ordering -----------
// (unchanged from R13/R15: WAIT0 -> sync -> prefetch -> compute; 64KB)
struct QKVOut {
    const float *bq, *bk, *bv;
    __half *qh, *kh, *vh;
};

#define G_LOAD(c) do {                                                       \
    uint32_t st_ = sb + ((c) & 1) * 32768;                                   \
    _Pragma("unroll")                                                        \
    for (int i_ = 0; i_ < 4; i_++) {                                         \
        int idx_ = tid + i_ * 256;                                           \
        int r_ = idx_ >> 3, u_ = idx_ & 7;                                   \
        uint32_t so_ = SW((uint32_t)(r_ * 128 + u_ * 16));                   \
        cp16(st_ + so_,         Ah + (size_t)(m0 + r_) * GK + (c) * 64 + u_ * 8); \
        cp16(st_ + 16384 + so_, Wh + (size_t)(n0 + r_) * GK + (c) * 64 + u_ * 8); \
    }                                                                        \
} while (0)

__global__ __launch_bounds__(256) void gemm1p(
    const __half* __restrict__ Ah, const __half* __restrict__ Whb, QKVOut op,
    const float* __restrict__ biasC, float* __restrict__ C, int mode)
{
    extern __shared__ char smc[];
    const uint32_t sb = smem_u32(smc);
    const int tid = threadIdx.x, lane = tid & 31, wid = tid >> 5;
    const int m0 = blockIdx.y * 128, n0 = blockIdx.x * 128;
    const int z = blockIdx.z;
    const __half* Wh = Whb + (mode ? (size_t)z * (GK * GN) : 0);
    const int wm = (wid & 3) * 32, wn = (wid >> 2) * 64;

    float acc[2][8][4];
#pragma unroll
    for (int mi = 0; mi < 2; mi++)
#pragma unroll
        for (int ni = 0; ni < 8; ni++)
#pragma unroll
            for (int r = 0; r < 4; r++) acc[mi][ni][r] = 0.0f;

    uint32_t aoff[2], boff[4];
#pragma unroll
    for (int mi = 0; mi < 2; mi++)
        aoff[mi] = (wm + mi * 16 + (lane & 15)) * 128 + ((lane >> 4) << 4);
#pragma unroll
    for (int nt = 0; nt < 4; nt++)
        boff[nt] = (wn + nt * 16 + (lane & 7) + ((lane >> 4) << 3)) * 128
                 + (((lane >> 3) & 1) << 4);

    G_LOAD(0); CP_COMMIT();

    for (int c = 0; c < 16; c++) {
        CP_WAIT0();                    // own copies of chunk c complete
        __syncthreads();               // chunk c visible; buf (c+1)&1 free
        if (c + 1 < 16) {
            G_LOAD(c + 1);
            CP_COMMIT();               // lands during compute(c)
        }

        const uint32_t sA = sb + (c & 1) * 32768;
        const uint32_t sW = sA + 16384;
#pragma unroll
        for (int k16 = 0; k16 < 4; k16++) {
            const uint32_t kb = k16 * 32;
            uint32_t a[2][4], w[4][4];
            ldsm4(a[0][0], a[0][1], a[0][2], a[0][3], sA + SW(aoff[0] + kb));
            ldsm4(a[1][0], a[1][1], a[1][2], a[1][3], sA + SW(aoff[1] + kb));
#pragma unroll
            for (int nt = 0; nt < 4; nt++)
                ldsm4(w[nt][0], w[nt][1], w[nt][2], w[nt][3],
                      sW + SW(boff[nt] + kb));
#pragma unroll
            for (int mi = 0; mi < 2; mi++)
#pragma unroll
                for (int ni = 0; ni < 8; ni++)
                    mma_f16(acc[mi][ni], a[mi],
                            w[ni >> 1][(ni & 1) * 2], w[ni >> 1][(ni & 1) * 2 + 1]);
        }
    }

    // epilogue
    const float* bias = mode ? ((z == 0) ? op.bq : (z == 1) ? op.bk : op.bv)
                             : biasC;
    const float osc = (mode == 1 && z == 0) ? SC2 : 1.0f;  // fold score scale
    const int r0 = lane >> 2, cq = (lane & 3) * 2;
#pragma unroll
    for (int mi = 0; mi < 2; mi++) {
#pragma unroll
        for (int ni = 0; ni < 8; ni++) {
            const int rr = m0 + wm + mi * 16 + r0;
            const int cc = n0 + wn + ni * 8 + cq;
            const float2 bv = *(const float2*)&bias[cc];
            float v0 = (acc[mi][ni][0] + bv.x) * osc;
            float v1 = (acc[mi][ni][1] + bv.y) * osc;
            float v2 = (acc[mi][ni][2] + bv.x) * osc;
            float v3 = (acc[mi][ni][3] + bv.y) * osc;
            if (mode == 0) {
                *(float2*)&C[(size_t)rr * GN + cc] = make_float2(v0, v1);
                *(float2*)&C[(size_t)(rr + 8) * GN + cc] = make_float2(v2, v3);
            } else {
                const int h = cc >> 6, d = cc & 63;
                const int bb = rr >> 11;
                const int s0 = rr & 2047, s1 = (rr + 8) & 2047;
                const size_t o0 = ((((size_t)bb * H_ + h) * S_ + s0) << 6) + d;
                const size_t o1 = ((((size_t)bb * H_ + h) * S_ + s1) << 6) + d;
                __half* oh = (z == 0) ? op.qh : (z == 1) ? op.kh : op.vh;
                *(uint32_t*)(oh + o0) = rn2(v0, v1);
                *(uint32_t*)(oh + o1) = rn2(v2, v3);
            }
        }
    }
}

// ---------------- f16 flash attention, paired q-tiles (load-balanced) -------
// CTA handles q-tiles i and 31-i -> uniform 33 tile-units per CTA;
// grid (16, 32) = 512 uniform CTAs (~1.15 waves at 3 CTAs/SM).
// Inner structure identical to R15: 2-stage pipeline, hoisted Q fragments,
// full-tile QK (8 streams) -> softmax -> PV. Fixed-shift base-2 softmax,
// l via all-ones mma. Q pre-scaled by SC2.
#define ATT_STAGE(kt) do {                                                   \
    uint32_t st_ = SST + ((kt) & 1) * 16384;                                 \
    const size_t roff_ = base + (size_t)((kt) * 64) * HD_;                   \
    _Pragma("unroll")                                                        \
    for (int i_ = 0; i_ < 4; i_++) {                                         \
        int idx_ = tid + i_ * 128;                                           \
        int r_ = idx_ >> 3, u_ = idx_ & 7;                                   \
        uint32_t so_ = SW((uint32_t)(r_ * 128 + u_ * 16));                   \
        size_t go_ = roff_ + (size_t)r_ * HD_ + u_ * 8;                      \
        cp16(st_ + so_,        Kh_ + go_);                                   \
        cp16(st_ + 8192 + so_, Vh_ + go_);                                   \
    }                                                                        \
    if (tid < 64)                                                            \
        smaskf[((kt) & 1) * 64 + tid] =                                      \
            (1.0f - mask[b * S_ + (kt) * 64 + tid]) * NEGM2 - MSHIFT;        \
} while (0)

__global__ __launch_bounds__(128) void attn_tc(
    const __half* __restrict__ Qh_, const __half* __restrict__ Kh_,
    const __half* __restrict__ Vh_, const float* __restrict__ mask,
    __half* __restrict__ ctxh)
{
    extern __shared__ char smraw[];
    const uint32_t sb = smem_u32(smraw);
    const uint32_t SQH = sb;                    // Q: 64 x 128B = 8KB
    const uint32_t SST = sb + 8192;             // 2 stages x 16KB
    float* smaskf = (float*)(smraw + 40960);    // 2 x 64 floats

    const int tid = threadIdx.x, lane = tid & 31, wid = tid >> 5;
    const int bh = blockIdx.y;
    const int b = bh >> 4, hh = bh & 15;
    const size_t base = (size_t)bh * (S_ * HD_);
    const int wq = wid * 16;

    const uint32_t arow = (wq + (lane & 15)) * 128 + ((lane >> 4) << 4);
    const uint32_t bno  = ((lane & 7) + ((lane >> 4) << 3)) * 128
                        + (((lane >> 3) & 1) << 4);
    const uint32_t vro  = (((lane >> 3) & 1) * 8 + (lane & 7)) * 128
                        + ((lane >> 4) << 4);
    const int c0 = (lane & 3) * 2;

#pragma unroll 1
    for (int part = 0; part < 2; part++) {
        const int qt = part ? (31 - blockIdx.x) : blockIdx.x;
        const int q0 = qt * 64;
        const int rg0 = q0 + wq + (lane >> 2);
        const int rg1 = rg0 + 8;
        const int ntile = qt + 1;

        __syncthreads();               // prior part's readers done (part 1)

        // Stage Q tile into smem (same cp.async group as stage 0)
        {
            const size_t qoff = base + (size_t)q0 * HD_;
#pragma unroll
            for (int i = 0; i < 4; i++) {
                int idx = tid + i * 128;
                int r = idx >> 3, u = idx & 7;
                cp16(SQH + SW((uint32_t)(r * 128 + u * 16)),
                     Qh_ + qoff + (size_t)r * HD_ + u * 8);
            }
        }
        ATT_STAGE(0);
        CP_COMMIT();

        uint32_t qf[4][4];                          // hoisted Q fragments
        float o[8][4];
#pragma unroll
        for (int ni = 0; ni < 8; ni++)
#pragma unroll
            for (int r = 0; r < 4; r++) o[ni][r] = 0.0f;
        float lacc[4] = {0.0f, 0.0f, 0.0f, 0.0f};   // row sums via ones-mma

        for (int kt = 0; kt < ntile; kt++) {
            CP_WAIT0();                // own copies of stage kt complete
            __syncthreads();           // stage kt visible; buf (kt+1)&1 free
            if (kt == 0) {             // Q resident: hoist fragments once
#pragma unroll
                for (int k16 = 0; k16 < 4; k16++)
                    ldsm4(qf[k16][0], qf[k16][1], qf[k16][2], qf[k16][3],
                          SQH + SW(arow + k16 * 32));
            }
            if (kt + 1 < ntile) {
                ATT_STAGE(kt + 1);
                CP_COMMIT();           // lands during compute(kt)
            }

            const int k0 = kt * 64;
            {
                const uint32_t sKh = SST + (kt & 1) * 16384;
                const uint32_t sVh = sKh + 8192;

                float s[8][4];
#pragma unroll
                for (int ni = 0; ni < 8; ni++)
#pragma unroll
                    for (int r = 0; r < 4; r++) s[ni][r] = 0.0f;

                // ---- S = Q.K (full tile: 8 independent streams) ----
#pragma unroll
                for (int k16 = 0; k16 < 4; k16++) {
                    const uint32_t kb = k16 * 32;
                    uint32_t kf[4][4];
#pragma unroll
                    for (int nt = 0; nt < 4; nt++)
                        ldsm4(kf[nt][0], kf[nt][1], kf[nt][2], kf[nt][3],
                              sKh + SW(bno + nt * 2048 + kb));
#pragma unroll
                    for (int ni = 0; ni < 8; ni++)
                        mma_f16(s[ni], qf[k16], kf[ni >> 1][(ni & 1) * 2],
                                kf[ni >> 1][(ni & 1) * 2 + 1]);
                }

                // ---- mask(+M shift) add + causal ----
                const float* mrow = smaskf + (kt & 1) * 64;
                const bool needc = (k0 + 63 > q0 + wq);
#pragma unroll
                for (int ni = 0; ni < 8; ni++) {
                    const int kg = k0 + ni * 8 + c0;
                    const float ma = mrow[ni * 8 + c0];
                    const float mb = mrow[ni * 8 + c0 + 1];
                    s[ni][0] += ma;
                    s[ni][1] += mb;
                    s[ni][2] += ma;
                    s[ni][3] += mb;
                    if (needc) {
                        if (kg > rg0)     s[ni][0] -= 1e10f;
                        if (kg + 1 > rg0) s[ni][1] -= 1e10f;
                        if (kg > rg1)     s[ni][2] -= 1e10f;
                        if (kg + 1 > rg1) s[ni][3] -= 1e10f;
                    }
                }

                // ---- P = 2^s; O += rn(P).V; l += rn(P).ones ----
#pragma unroll
                for (int jb = 0; jb < 4; jb++) {
                    uint32_t aP[4];
#pragma unroll
                    for (int t = 0; t < 2; t++) {
                        const int ti = jb * 2 + t;
                        aP[t * 2 + 0] = rn2(ex2f(s[ti][0]), ex2f(s[ti][1]));
                        aP[t * 2 + 1] = rn2(ex2f(s[ti][2]), ex2f(s[ti][3]));
                    }
                    uint32_t vf[4][4];
                    const uint32_t vbase = vro + jb * 2048;
#pragma unroll
                    for (int nt = 0; nt < 4; nt++)
                        ldsm4t(vf[nt], sVh + SW(vbase + nt * 32));
#pragma unroll
                    for (int ni = 0; ni < 8; ni++)
                        mma_f16(o[ni], aP, vf[ni >> 1][(ni & 1) * 2],
                                vf[ni >> 1][(ni & 1) * 2 + 1]);
                    mma_f16(lacc, aP, ONES2, ONES2);
                }
            }
        }

        // ---- normalize + write ctx rn(f16) in [B,S,D] layout ----
        const float i0 = 1.0f / lacc[0], i1 = 1.0f / lacc[2];
        const size_t row0 = ((size_t)b * S_ + rg0) * D_ + hh * HD_;
        const size_t row1 = ((size_t)b * S_ + rg1) * D_ + hh * HD_;
#pragma unroll
        for (int ni = 0; ni < 8; ni++) {
            const int d = ni * 8 + c0;
            *(uint32_t*)(ctxh + row0 + d) = rn2(o[ni][0] * i0, o[ni][1] * i0);
            *(uint32_t*)(ctxh + row1 + d) = rn2(o[ni][2] * i1, o[ni][3] * i1);
        }
    }
}

// ---------------------------------------------------------------------------
extern "C" void kernel_launch(void* const* d_in, const int* in_sizes, int n_in,
                              void* d_out, int out_size)
{
    const float* X    = (const float*)d_in[0];
    const float* mask = (const float*)d_in[1];
    const float* Wq   = (const float*)d_in[2];
    const float* bq   = (const float*)d_in[3];
    const float* Wk   = (const float*)d_in[4];
    const float* bk   = (const float*)d_in[5];
    const float* Wv   = (const float*)d_in[6];
    const float* bv   = (const float*)d_in[7];
    const float* Wo   = (const float*)d_in[8];
    const float* bo   = (const float*)d_in[9];
    float* out = (float*)d_out;

    __half *pXh, *pWh, *pQh, *pKh, *pVh, *pCh;
    cudaGetSymbolAddress((void**)&pXh, g_Xh);
    cudaGetSymbolAddress((void**)&pWh, g_Wh);
    cudaGetSymbolAddress((void**)&pQh, g_Qh);
    cudaGetSymbolAddress((void**)&pKh, g_Kh);
    cudaGetSymbolAddress((void**)&pVh, g_Vh);
    cudaGetSymbolAddress((void**)&pCh, g_Ch);

    const int GEMM_SMEM = 2 * 32768;                 // 64 KB
    cudaFuncSetAttribute(gemm1p, cudaFuncAttributeMaxDynamicSharedMemorySize,
                         GEMM_SMEM);
    const int ATTN_SMEM = 40960 + 512;               // 40.5 KB
    cudaFuncSetAttribute(attn_tc, cudaFuncAttributeMaxDynamicSharedMemorySize,
                         ATTN_SMEM);

    const size_t WSZ = (size_t)GK * GN;

    rn_f16<<<M_ * GK / 1024, 256>>>(X, pXh);
    WPtrs ws = {{Wq, Wk, Wv, Wo}};
    transpose_w_all<<<dim3(GN / 32, GK / 32, 4), dim3(32, 8)>>>(ws, pWh);

    QKVOut op = {bq, bk, bv, pQh, pKh, pVh};
    gemm1p<<<dim3(GN / 128, M_ / 128, 3), 256, GEMM_SMEM>>>(
        pXh, pWh, op, nullptr, nullptr, 1);

    dim3 ga(16, B_ * H_);          // paired q-tiles: uniform 512 CTAs
    attn_tc<<<ga, 128, ATTN_SMEM>>>(pQh, pKh, pVh, mask, pCh);

    gemm1p<<<dim3(GN / 128, M_ / 128, 1), 256, GEMM_SMEM>>>(
        pCh, pWh + 3 * WSZ, op, bo, out, 0);
}